// round 4
// baseline (speedup 1.0000x reference)
#include <cuda_runtime.h>
#include <cuda_bf16.h>
#include <cstdint>

// ---------------------------------------------------------------------------
// CFModule_12575664243188 on sm_103a (compute_103-safe: no tcgen05):
//   x: [B=16, H=256, W=256, C=64] fp32
//   pooled = adaptive_avg_pool 4x4  -> [B,16,64]
//   dots[b,i,j] = 0.25 * <pooled[:,i], pooled[:,j]>; attn = softmax_j
//   out[b,s,t] = gelu_erf( sum_c x[b,s,c] * attn[b,t,c] )
//
// Main GEMM: mma.sync m16n8k16 bf16, 2-term split precision (hi+lo),
// 4 accumulated MMA products (hh + lh + hl + ll), fp32 accumulate.
// A fragments are loaded straight from global memory (no X smem staging).
// ---------------------------------------------------------------------------

#define B_    16
#define Hc    256
#define Wc    256
#define Cc    64
#define HW    (Hc*Wc)          // 65536
#define TILE_S 128

// --------------------------- global scratch --------------------------------
__device__ float g_pp[1024 * 64];                    // pool partials [b][n][q][c]
__device__ uint4 g_attn_h4[B_ * 512];                // attn hi bf16 [b][t][c]
__device__ uint4 g_attn_l4[B_ * 512];                // attn lo bf16

// --------------------------- helpers ---------------------------------------
__device__ __forceinline__ uint32_t smem_u32(const void* p) {
    uint32_t a;
    asm("{ .reg .u64 t; cvta.to.shared.u64 t, %1; cvt.u32.u64 %0, t; }"
        : "=r"(a) : "l"(p));
    return a;
}

__device__ __forceinline__ void ldsm_x4(uint32_t& r0, uint32_t& r1,
                                        uint32_t& r2, uint32_t& r3, uint32_t addr) {
    asm volatile("ldmatrix.sync.aligned.m8n8.x4.shared.b16 {%0,%1,%2,%3}, [%4];"
                 : "=r"(r0), "=r"(r1), "=r"(r2), "=r"(r3) : "r"(addr));
}

__device__ __forceinline__ void mma_bf16(float* c, uint32_t a0, uint32_t a1,
                                         uint32_t a2, uint32_t a3,
                                         uint32_t b0, uint32_t b1) {
    asm volatile(
        "mma.sync.aligned.m16n8k16.row.col.f32.bf16.bf16.f32 "
        "{%0,%1,%2,%3}, {%4,%5,%6,%7}, {%8,%9}, {%0,%1,%2,%3};"
        : "+f"(c[0]), "+f"(c[1]), "+f"(c[2]), "+f"(c[3])
        : "r"(a0), "r"(a1), "r"(a2), "r"(a3), "r"(b0), "r"(b1));
}

// pack two fp32 -> bf16x2 (first arg -> low 16 bits)
__device__ __forceinline__ uint32_t pack_bf(float lo_val, float hi_val) {
    uint32_t r;
    asm("cvt.rn.bf16x2.f32 %0, %1, %2;" : "=r"(r) : "f"(hi_val), "f"(lo_val));
    return r;
}

__device__ __forceinline__ float gelu_erf(float v) {
    return 0.5f * v * (1.0f + erff(v * 0.70710678118654752f));
}

// ---------------------------------------------------------------------------
// Kernel A: pool partials. grid = 1024 (b*64 + n*4 + q), 256 threads.
// ---------------------------------------------------------------------------
__global__ void __launch_bounds__(256) pool_kernel(const float* __restrict__ x)
{
    int blk = blockIdx.x;
    int q = blk & 3, n = (blk >> 2) & 15, b = blk >> 6;
    int ph = n >> 2, pw = n & 3;
    int tid = threadIdx.x;

    float4 acc = make_float4(0.f, 0.f, 0.f, 0.f);
    for (int hh = 0; hh < 16; ++hh) {
        int h = ph * 64 + q * 16 + hh;
        const float4* row = (const float4*)(
            x + (((size_t)b * Hc + h) * Wc + (size_t)pw * 64) * Cc);
        #pragma unroll
        for (int it = 0; it < 4; ++it) {
            float4 v = row[tid + 256 * it];
            acc.x += v.x; acc.y += v.y; acc.z += v.z; acc.w += v.w;
        }
    }
    __shared__ float4 sm[256];
    sm[tid] = acc;
    __syncthreads();
    if (tid < 64) {
        int r = tid >> 2, j = tid & 3;
        float s = 0.f;
        #pragma unroll
        for (int w = 0; w < 16; ++w)
            s += ((const float*)&sm[r + 16 * w])[j];
        g_pp[blk * 64 + tid] = s;
    }
}

// ---------------------------------------------------------------------------
// Kernel B: merge partials, gram + softmax, emit bf16 hi/lo attn.
// ---------------------------------------------------------------------------
__global__ void __launch_bounds__(64) attn_kernel()
{
    int b = blockIdx.x;
    int i = threadIdx.x;
    __shared__ float xs[64][17];
    float my[16];
    #pragma unroll
    for (int n = 0; n < 16; ++n) {
        int base = ((b * 16 + n) * 4) * 64 + i;
        float v = (g_pp[base] + g_pp[base + 64] + g_pp[base + 128] + g_pp[base + 192])
                  * (1.0f / 4096.0f);
        xs[i][n] = v;
        my[n] = v;
    }
    __syncthreads();

    float d[64];
    float mx = -1e30f;
    #pragma unroll
    for (int j = 0; j < 64; ++j) {
        float s = 0.f;
        #pragma unroll
        for (int n = 0; n < 16; ++n) s += my[n] * xs[j][n];
        s *= 0.25f;
        d[j] = s;
        mx = fmaxf(mx, s);
    }
    float sum = 0.f;
    #pragma unroll
    for (int j = 0; j < 64; ++j) { d[j] = expf(d[j] - mx); sum += d[j]; }
    float inv = 1.0f / sum;

    __nv_bfloat16* ah = (__nv_bfloat16*)g_attn_h4;
    __nv_bfloat16* al = (__nv_bfloat16*)g_attn_l4;
    size_t rb = ((size_t)b * 64 + i) * 64;
    #pragma unroll
    for (int j = 0; j < 64; ++j) {
        float a = d[j] * inv;
        __nv_bfloat16 h = __float2bfloat16(a);
        float hv = __bfloat162float(h);
        ah[rb + j] = h;
        al[rb + j] = __float2bfloat16(a - hv);
    }
}

// ---------------------------------------------------------------------------
// Kernel C: mma.sync bf16 GEMM + exact-erf GELU.
// grid = (HW/128, B), 256 threads (8 warps). D[128x64] = X[128x64] * Attn^T.
// Warp w owns M-rows [w*16, w*16+16).
// A fragments: loaded directly from global (LDG.64 per bf16x2 pair),
// converted to hi/lo bf16 in registers. B (attn) hi/lo staged in 16KB smem,
// consumed with swizzled ldmatrix.
//
// m16n8k16 A-fragment layout (g = lane>>2, t = lane&3), k-chunk kc:
//   a0 = (row g,    cols kc*16 + 2t, +1)     a1 = (row g+8, same cols)
//   a2 = (row g,    cols kc*16+8+2t, +1)     a3 = (row g+8, same cols)
// ---------------------------------------------------------------------------
#define OFF_BH 0
#define OFF_BL 8192

__global__ void __launch_bounds__(256) gemm_kernel(const float* __restrict__ x,
                                                   float* __restrict__ out)
{
    __shared__ __align__(128) unsigned char smem[16384];
    uint32_t sb = smem_u32(smem);
    int tid = threadIdx.x;
    int wid = tid >> 5, lid = tid & 31;
    int b = blockIdx.y;
    int s0 = blockIdx.x * TILE_S;

    // ---- attn tile [64x64] bf16 hi/lo -> swizzled smem (512 uint4 each)
    const uint4* gh = g_attn_h4 + (size_t)b * 512;
    const uint4* gl = g_attn_l4 + (size_t)b * 512;
    #pragma unroll
    for (int it = 0; it < 2; ++it) {
        int m = tid + 256 * it;               // uint4 index (512 total)
        int row = m >> 3;
        uint32_t kbyte = (m & 7) * 16;
        uint32_t off = row * 128 + (kbyte ^ ((row & 7) << 4));
        *(uint4*)(smem + OFF_BH + off) = gh[m];
        *(uint4*)(smem + OFF_BL + off) = gl[m];
    }

    // ---- A fragments straight from global, convert to bf16 hi/lo in regs
    int g = lid >> 2, t2 = (lid & 3) * 2;
    const float* xr0 = x + ((size_t)b * HW + s0 + wid * 16 + g) * Cc;
    const float* xr1 = xr0 + 8 * Cc;

    uint32_t ah[16], al[16];                  // [kc][frag 0..3]
    #pragma unroll
    for (int kc = 0; kc < 4; ++kc) {
        float2 v0 = __ldcs((const float2*)(xr0 + kc * 16 + t2));
        float2 v1 = __ldcs((const float2*)(xr1 + kc * 16 + t2));
        float2 v2 = __ldcs((const float2*)(xr0 + kc * 16 + 8 + t2));
        float2 v3 = __ldcs((const float2*)(xr1 + kc * 16 + 8 + t2));
        #pragma unroll
        for (int f = 0; f < 4; ++f) {
            float2 v = f == 0 ? v0 : (f == 1 ? v1 : (f == 2 ? v2 : v3));
            uint32_t h = pack_bf(v.x, v.y);
            float hx = __uint_as_float(h << 16);
            float hy = __uint_as_float(h & 0xFFFF0000u);
            ah[kc * 4 + f] = h;
            al[kc * 4 + f] = pack_bf(v.x - hx, v.y - hy);
        }
    }
    __syncthreads();

    // ---- MMA mainloop
    float acc[8][4];
    #pragma unroll
    for (int i = 0; i < 8; ++i)
        #pragma unroll
        for (int j = 0; j < 4; ++j) acc[i][j] = 0.f;

    uint32_t b_nrow_lo = (lid & 7) + ((lid >> 4) & 1) * 8;
    uint32_t b_k16 = (lid >> 3) & 1;

    #pragma unroll
    for (int kc = 0; kc < 4; ++kc) {
        uint32_t kb = kc * 32;
        uint32_t A0 = ah[kc * 4 + 0], A1 = ah[kc * 4 + 1],
                 A2 = ah[kc * 4 + 2], A3 = ah[kc * 4 + 3];
        uint32_t L0 = al[kc * 4 + 0], L1 = al[kc * 4 + 1],
                 L2 = al[kc * 4 + 2], L3 = al[kc * 4 + 3];
        #pragma unroll
        for (int ntp = 0; ntp < 4; ++ntp) {
            uint32_t bn = ntp * 16 + b_nrow_lo;
            uint32_t bkb = kb + b_k16 * 16;
            uint32_t b_off = bn * 128 + (bkb ^ ((bn & 7) << 4));
            uint32_t bh0, bh1, bh2, bh3, bl0, bl1, bl2, bl3;
            ldsm_x4(bh0, bh1, bh2, bh3, sb + OFF_BH + b_off);
            ldsm_x4(bl0, bl1, bl2, bl3, sb + OFF_BL + b_off);

            float* c0 = acc[ntp * 2];
            float* c1 = acc[ntp * 2 + 1];
            mma_bf16(c0, A0, A1, A2, A3, bh0, bh1);
            mma_bf16(c0, L0, L1, L2, L3, bh0, bh1);
            mma_bf16(c0, A0, A1, A2, A3, bl0, bl1);
            mma_bf16(c0, L0, L1, L2, L3, bl0, bl1);
            mma_bf16(c1, A0, A1, A2, A3, bh2, bh3);
            mma_bf16(c1, L0, L1, L2, L3, bh2, bh3);
            mma_bf16(c1, A0, A1, A2, A3, bl2, bl3);
            mma_bf16(c1, L0, L1, L2, L3, bl2, bl3);
        }
    }

    // ---- epilogue: GELU + store (evict-first; out never re-read)
    float* ob = out + ((size_t)b * HW + s0) * Cc;
    int r0 = wid * 16 + (lid >> 2);
    int cbase = (lid & 3) * 2;
    #pragma unroll
    for (int nt = 0; nt < 8; ++nt) {
        int col = nt * 8 + cbase;
        float2 v0, v1;
        v0.x = gelu_erf(acc[nt][0]);
        v0.y = gelu_erf(acc[nt][1]);
        v1.x = gelu_erf(acc[nt][2]);
        v1.y = gelu_erf(acc[nt][3]);
        __stcs((float2*)(ob + (size_t)r0 * Cc + col), v0);
        __stcs((float2*)(ob + (size_t)(r0 + 8) * Cc + col), v1);
    }
}

// ---------------------------------------------------------------------------
extern "C" void kernel_launch(void* const* d_in, const int* in_sizes, int n_in,
                              void* d_out, int out_size)
{
    const float* x = (const float*)d_in[0];
    float* out = (float*)d_out;
    (void)in_sizes; (void)n_in; (void)out_size;

    pool_kernel<<<1024, 256>>>(x);
    attn_kernel<<<B_, 64>>>();
    gemm_kernel<<<dim3(HW / TILE_S, B_), 256>>>(x, out);
}

// round 5
// speedup vs baseline: 1.2119x; 1.2119x over previous
#include <cuda_runtime.h>
#include <cuda_bf16.h>
#include <cstdint>

// ---------------------------------------------------------------------------
// CFModule_12575664243188 on sm_103a (compute_103-safe: no tcgen05):
//   x: [B=16, H=256, W=256, C=64] fp32
//   pooled = adaptive_avg_pool 4x4  -> [B,16,64]
//   dots[b,i,j] = 0.25 * <pooled[:,i], pooled[:,j]>; attn = softmax_j
//   out[b,s,t] = gelu( sum_c x[b,s,c] * attn[b,t,c] )
//
// Main GEMM: mma.sync m16n8k16 bf16, 2-term split precision (hi+lo),
// 3 accumulated MMA products (hh + lh + hl), fp32 accumulate.
// GELU epilogue via single-instruction tanh.approx.f32.
// ---------------------------------------------------------------------------

#define B_    16
#define Hc    256
#define Wc    256
#define Cc    64
#define HW    (Hc*Wc)          // 65536
#define TILE_S 128

// --------------------------- global scratch --------------------------------
__device__ float g_pp[1024 * 64];                    // pool partials [b][n][q][c]
__device__ uint4 g_attn_h4[B_ * 512];                // attn hi bf16 [b][t][c]
__device__ uint4 g_attn_l4[B_ * 512];                // attn lo bf16

// --------------------------- helpers ---------------------------------------
__device__ __forceinline__ uint32_t smem_u32(const void* p) {
    uint32_t a;
    asm("{ .reg .u64 t; cvta.to.shared.u64 t, %1; cvt.u32.u64 %0, t; }"
        : "=r"(a) : "l"(p));
    return a;
}

__device__ __forceinline__ void ldsm_x4(uint32_t& r0, uint32_t& r1,
                                        uint32_t& r2, uint32_t& r3, uint32_t addr) {
    asm volatile("ldmatrix.sync.aligned.m8n8.x4.shared.b16 {%0,%1,%2,%3}, [%4];"
                 : "=r"(r0), "=r"(r1), "=r"(r2), "=r"(r3) : "r"(addr));
}

__device__ __forceinline__ void mma_bf16(float* c, uint32_t a0, uint32_t a1,
                                         uint32_t a2, uint32_t a3,
                                         uint32_t b0, uint32_t b1) {
    asm volatile(
        "mma.sync.aligned.m16n8k16.row.col.f32.bf16.bf16.f32 "
        "{%0,%1,%2,%3}, {%4,%5,%6,%7}, {%8,%9}, {%0,%1,%2,%3};"
        : "+f"(c[0]), "+f"(c[1]), "+f"(c[2]), "+f"(c[3])
        : "r"(a0), "r"(a1), "r"(a2), "r"(a3), "r"(b0), "r"(b1));
}

// pack two fp32 -> bf16x2 (first arg -> low 16 bits)
__device__ __forceinline__ uint32_t pack_bf(float lo_val, float hi_val) {
    uint32_t r;
    asm("cvt.rn.bf16x2.f32 %0, %1, %2;" : "=r"(r) : "f"(hi_val), "f"(lo_val));
    return r;
}

// GELU via HW tanh: 0.5*v*(1 + tanh(0.79788456*(v + 0.044715 v^3)))
__device__ __forceinline__ float gelu_fast(float v) {
    float v2 = v * v;
    float p = fmaf(0.0356774081f, v2, 0.7978845608f);   // 0.79788456*(1+0.044715 v^2)/... 
    float arg = p * v;
    float t;
    asm("tanh.approx.f32 %0, %1;" : "=f"(t) : "f"(arg));
    float h = 0.5f * v;
    return fmaf(h, t, h);
}

// ---------------------------------------------------------------------------
// Kernel A: pool partials. grid = 1024 (b*64 + n*4 + q), 256 threads.
// ---------------------------------------------------------------------------
__global__ void __launch_bounds__(256) pool_kernel(const float* __restrict__ x)
{
    int blk = blockIdx.x;
    int q = blk & 3, n = (blk >> 2) & 15, b = blk >> 6;
    int ph = n >> 2, pw = n & 3;
    int tid = threadIdx.x;

    float4 acc = make_float4(0.f, 0.f, 0.f, 0.f);
    for (int hh = 0; hh < 16; ++hh) {
        int h = ph * 64 + q * 16 + hh;
        const float4* row = (const float4*)(
            x + (((size_t)b * Hc + h) * Wc + (size_t)pw * 64) * Cc);
        #pragma unroll
        for (int it = 0; it < 4; ++it) {
            float4 v = row[tid + 256 * it];
            acc.x += v.x; acc.y += v.y; acc.z += v.z; acc.w += v.w;
        }
    }
    __shared__ float4 sm[256];
    sm[tid] = acc;
    __syncthreads();
    if (tid < 64) {
        int r = tid >> 2, j = tid & 3;
        float s = 0.f;
        #pragma unroll
        for (int w = 0; w < 16; ++w)
            s += ((const float*)&sm[r + 16 * w])[j];
        g_pp[blk * 64 + tid] = s;
    }
}

// ---------------------------------------------------------------------------
// Kernel B: merge partials, gram + softmax, emit bf16 hi/lo attn.
// ---------------------------------------------------------------------------
__global__ void __launch_bounds__(64) attn_kernel()
{
    int b = blockIdx.x;
    int i = threadIdx.x;
    __shared__ float xs[64][17];
    float my[16];
    #pragma unroll
    for (int n = 0; n < 16; ++n) {
        int base = ((b * 16 + n) * 4) * 64 + i;
        float v = (g_pp[base] + g_pp[base + 64] + g_pp[base + 128] + g_pp[base + 192])
                  * (1.0f / 4096.0f);
        xs[i][n] = v;
        my[n] = v;
    }
    __syncthreads();

    float d[64];
    float mx = -1e30f;
    #pragma unroll
    for (int j = 0; j < 64; ++j) {
        float s = 0.f;
        #pragma unroll
        for (int n = 0; n < 16; ++n) s += my[n] * xs[j][n];
        s *= 0.25f;
        d[j] = s;
        mx = fmaxf(mx, s);
    }
    float sum = 0.f;
    #pragma unroll
    for (int j = 0; j < 64; ++j) { d[j] = expf(d[j] - mx); sum += d[j]; }
    float inv = 1.0f / sum;

    __nv_bfloat16* ah = (__nv_bfloat16*)g_attn_h4;
    __nv_bfloat16* al = (__nv_bfloat16*)g_attn_l4;
    size_t rb = ((size_t)b * 64 + i) * 64;
    #pragma unroll
    for (int j = 0; j < 64; ++j) {
        float a = d[j] * inv;
        __nv_bfloat16 h = __float2bfloat16(a);
        float hv = __bfloat162float(h);
        ah[rb + j] = h;
        al[rb + j] = __float2bfloat16(a - hv);
    }
}

// ---------------------------------------------------------------------------
// Kernel C: mma.sync bf16 GEMM + fast GELU.
// grid = (HW/128, B), 256 threads (8 warps). D[128x64] = X[128x64] * Attn^T.
// Warp w owns M-rows [w*16, w*16+16). Split: D = Xh*Ah + Xl*Ah + Xh*Al.
//
// SMEM (static 48KB): BH [64][64] bf16 (8KB), BL (8KB),
//                     XH [128][64] bf16 (16KB), XL (16KB)
// All tiles: 128B rows, 16B-granular XOR swizzle:
//   off(row, kbyte) = row*128 + (kbyte ^ ((row&7)<<4))
// ---------------------------------------------------------------------------
#define OFF_BH 0
#define OFF_BL 8192
#define OFF_XH 16384
#define OFF_XL 32768

__global__ void __launch_bounds__(256, 3) gemm_kernel(const float* __restrict__ x,
                                                      float* __restrict__ out)
{
    __shared__ __align__(128) unsigned char smem[49152];
    uint32_t sb = smem_u32(smem);
    int tid = threadIdx.x;
    int wid = tid >> 5, lid = tid & 31;
    int b = blockIdx.y;
    int s0 = blockIdx.x * TILE_S;

    // ---- issue all global loads first (max MLP)
    const float4* gx = (const float4*)(x + ((size_t)b * HW + s0) * Cc);
    float4 v[8];
    #pragma unroll
    for (int it = 0; it < 8; ++it) v[it] = __ldcs(&gx[tid + 256 * it]);

    const uint4* gh = g_attn_h4 + (size_t)b * 512;
    const uint4* gl = g_attn_l4 + (size_t)b * 512;
    uint4 bh0 = gh[tid], bh1 = gh[tid + 256];
    uint4 bl0 = gl[tid], bl1 = gl[tid + 256];

    // ---- convert x tile to bf16 hi/lo, store swizzled
    #pragma unroll
    for (int it = 0; it < 8; ++it) {
        int f = tid + 256 * it;               // float4 index (2048 total)
        uint32_t p0 = pack_bf(v[it].x, v[it].y);
        uint32_t p1 = pack_bf(v[it].z, v[it].w);
        float hx = __uint_as_float(p0 << 16);
        float hy = __uint_as_float(p0 & 0xFFFF0000u);
        float hz = __uint_as_float(p1 << 16);
        float hw = __uint_as_float(p1 & 0xFFFF0000u);
        uint32_t q0 = pack_bf(v[it].x - hx, v[it].y - hy);
        uint32_t q1 = pack_bf(v[it].z - hz, v[it].w - hw);
        int row = f >> 4;
        uint32_t kbyte = (f & 15) * 8;
        uint32_t off = row * 128 + (kbyte ^ ((row & 7) << 4));
        *(uint2*)(smem + OFF_XH + off) = make_uint2(p0, p1);
        *(uint2*)(smem + OFF_XL + off) = make_uint2(q0, q1);
    }

    // ---- attn tiles, store swizzled
    {
        int m0 = tid, m1 = tid + 256;
        int row0 = m0 >> 3, row1 = m1 >> 3;
        uint32_t kb0 = (m0 & 7) * 16, kb1 = (m1 & 7) * 16;
        uint32_t o0 = row0 * 128 + (kb0 ^ ((row0 & 7) << 4));
        uint32_t o1 = row1 * 128 + (kb1 ^ ((row1 & 7) << 4));
        *(uint4*)(smem + OFF_BH + o0) = bh0;
        *(uint4*)(smem + OFF_BH + o1) = bh1;
        *(uint4*)(smem + OFF_BL + o0) = bl0;
        *(uint4*)(smem + OFF_BL + o1) = bl1;
    }
    __syncthreads();

    // ---- MMA mainloop
    float acc[8][4];
    #pragma unroll
    for (int i = 0; i < 8; ++i)
        #pragma unroll
        for (int j = 0; j < 4; ++j) acc[i][j] = 0.f;

    uint32_t a_row = wid * 16 + (lid & 15);
    uint32_t a_k16 = (lid >> 4) & 1;
    uint32_t b_nrow_lo = (lid & 7) + ((lid >> 4) & 1) * 8;
    uint32_t b_k16 = (lid >> 3) & 1;

    #pragma unroll
    for (int kc = 0; kc < 4; ++kc) {
        uint32_t kb = kc * 32;
        uint32_t akb = kb + a_k16 * 16;
        uint32_t a_off = a_row * 128 + (akb ^ ((a_row & 7) << 4));
        uint32_t A0, A1, A2, A3, L0, L1, L2, L3;
        ldsm_x4(A0, A1, A2, A3, sb + OFF_XH + a_off);
        ldsm_x4(L0, L1, L2, L3, sb + OFF_XL + a_off);

        #pragma unroll
        for (int ntp = 0; ntp < 4; ++ntp) {
            uint32_t bn = ntp * 16 + b_nrow_lo;
            uint32_t bkb = kb + b_k16 * 16;
            uint32_t b_off = bn * 128 + (bkb ^ ((bn & 7) << 4));
            uint32_t h0, h1, h2, h3, l0, l1, l2, l3;
            ldsm_x4(h0, h1, h2, h3, sb + OFF_BH + b_off);
            ldsm_x4(l0, l1, l2, l3, sb + OFF_BL + b_off);

            float* c0 = acc[ntp * 2];
            float* c1 = acc[ntp * 2 + 1];
            mma_bf16(c0, A0, A1, A2, A3, h0, h1);
            mma_bf16(c0, L0, L1, L2, L3, h0, h1);
            mma_bf16(c0, A0, A1, A2, A3, l0, l1);
            mma_bf16(c1, A0, A1, A2, A3, h2, h3);
            mma_bf16(c1, L0, L1, L2, L3, h2, h3);
            mma_bf16(c1, A0, A1, A2, A3, l2, l3);
        }
    }

    // ---- epilogue: fast GELU + store (evict-first; out never re-read)
    float* ob = out + ((size_t)b * HW + s0) * Cc;
    int r0 = wid * 16 + (lid >> 2);
    int cbase = (lid & 3) * 2;
    #pragma unroll
    for (int nt = 0; nt < 8; ++nt) {
        int col = nt * 8 + cbase;
        float2 v0, v1;
        v0.x = gelu_fast(acc[nt][0]);
        v0.y = gelu_fast(acc[nt][1]);
        v1.x = gelu_fast(acc[nt][2]);
        v1.y = gelu_fast(acc[nt][3]);
        __stcs((float2*)(ob + (size_t)r0 * Cc + col), v0);
        __stcs((float2*)(ob + (size_t)(r0 + 8) * Cc + col), v1);
    }
}

// ---------------------------------------------------------------------------
extern "C" void kernel_launch(void* const* d_in, const int* in_sizes, int n_in,
                              void* d_out, int out_size)
{
    const float* x = (const float*)d_in[0];
    float* out = (float*)d_out;
    (void)in_sizes; (void)n_in; (void)out_size;

    pool_kernel<<<1024, 256>>>(x);
    attn_kernel<<<B_, 64>>>();
    gemm_kernel<<<dim3(HW / TILE_S, B_), 256>>>(x, out);
}

// round 6
// speedup vs baseline: 1.2517x; 1.0328x over previous
#include <cuda_runtime.h>
#include <cuda_bf16.h>
#include <cstdint>

// ---------------------------------------------------------------------------
// CFModule_12575664243188 on sm_103a (compute_103-safe: no tcgen05):
//   x: [B=16, H=256, W=256, C=64] fp32
//   pooled = adaptive_avg_pool 4x4  -> [B,16,64]
//   dots[b,i,j] = 0.25 * <pooled[:,i], pooled[:,j]>; attn = softmax_j
//   out[b,s,t] = gelu( sum_c x[b,s,c] * attn[b,t,c] )
//
// Main GEMM: mma.sync m16n8k16 bf16, 2-term split precision (hi+lo),
// 3 accumulated MMA products (hh + lh + hl), fp32 accumulate.
// GELU via tanh.approx.f32; output staged through smem for STG.128 stores.
// ---------------------------------------------------------------------------

#define B_    16
#define Hc    256
#define Wc    256
#define Cc    64
#define HW    (Hc*Wc)          // 65536
#define TILE_S 128

// --------------------------- global scratch --------------------------------
__device__ float g_pp[1024 * 64];                    // pool partials [b][n][q][c]
__device__ uint4 g_attn_h4[B_ * 512];                // attn hi bf16 [b][t][c]
__device__ uint4 g_attn_l4[B_ * 512];                // attn lo bf16

// --------------------------- helpers ---------------------------------------
__device__ __forceinline__ uint32_t smem_u32(const void* p) {
    uint32_t a;
    asm("{ .reg .u64 t; cvta.to.shared.u64 t, %1; cvt.u32.u64 %0, t; }"
        : "=r"(a) : "l"(p));
    return a;
}

__device__ __forceinline__ void ldsm_x4(uint32_t& r0, uint32_t& r1,
                                        uint32_t& r2, uint32_t& r3, uint32_t addr) {
    asm volatile("ldmatrix.sync.aligned.m8n8.x4.shared.b16 {%0,%1,%2,%3}, [%4];"
                 : "=r"(r0), "=r"(r1), "=r"(r2), "=r"(r3) : "r"(addr));
}

__device__ __forceinline__ void mma_bf16(float* c, uint32_t a0, uint32_t a1,
                                         uint32_t a2, uint32_t a3,
                                         uint32_t b0, uint32_t b1) {
    asm volatile(
        "mma.sync.aligned.m16n8k16.row.col.f32.bf16.bf16.f32 "
        "{%0,%1,%2,%3}, {%4,%5,%6,%7}, {%8,%9}, {%0,%1,%2,%3};"
        : "+f"(c[0]), "+f"(c[1]), "+f"(c[2]), "+f"(c[3])
        : "r"(a0), "r"(a1), "r"(a2), "r"(a3), "r"(b0), "r"(b1));
}

// pack two fp32 -> bf16x2 (first arg -> low 16 bits)
__device__ __forceinline__ uint32_t pack_bf(float lo_val, float hi_val) {
    uint32_t r;
    asm("cvt.rn.bf16x2.f32 %0, %1, %2;" : "=r"(r) : "f"(hi_val), "f"(lo_val));
    return r;
}

// GELU via HW tanh: 0.5*v*(1 + tanh(0.79788456*(v + 0.044715 v^3)))
__device__ __forceinline__ float gelu_fast(float v) {
    float v2 = v * v;
    float p = fmaf(0.0356774081f, v2, 0.7978845608f);
    float arg = p * v;
    float t;
    asm("tanh.approx.f32 %0, %1;" : "=f"(t) : "f"(arg));
    float h = 0.5f * v;
    return fmaf(h, t, h);
}

// ---------------------------------------------------------------------------
// Kernel A: pool partials. grid = 1024 (b*64 + n*4 + q), 256 threads.
// ---------------------------------------------------------------------------
__global__ void __launch_bounds__(256) pool_kernel(const float* __restrict__ x)
{
    int blk = blockIdx.x;
    int q = blk & 3, n = (blk >> 2) & 15, b = blk >> 6;
    int ph = n >> 2, pw = n & 3;
    int tid = threadIdx.x;

    float4 acc = make_float4(0.f, 0.f, 0.f, 0.f);
    for (int hh = 0; hh < 16; ++hh) {
        int h = ph * 64 + q * 16 + hh;
        const float4* row = (const float4*)(
            x + (((size_t)b * Hc + h) * Wc + (size_t)pw * 64) * Cc);
        #pragma unroll
        for (int it = 0; it < 4; ++it) {
            float4 v = row[tid + 256 * it];
            acc.x += v.x; acc.y += v.y; acc.z += v.z; acc.w += v.w;
        }
    }
    __shared__ float4 sm[256];
    sm[tid] = acc;
    __syncthreads();
    if (tid < 64) {
        int r = tid >> 2, j = tid & 3;
        float s = 0.f;
        #pragma unroll
        for (int w = 0; w < 16; ++w)
            s += ((const float*)&sm[r + 16 * w])[j];
        g_pp[blk * 64 + tid] = s;
    }
}

// ---------------------------------------------------------------------------
// Kernel B: merge partials, gram + softmax, emit bf16 hi/lo attn.
// ---------------------------------------------------------------------------
__global__ void __launch_bounds__(64) attn_kernel()
{
    int b = blockIdx.x;
    int i = threadIdx.x;
    __shared__ float xs[64][17];
    float my[16];
    #pragma unroll
    for (int n = 0; n < 16; ++n) {
        int base = ((b * 16 + n) * 4) * 64 + i;
        float v = (g_pp[base] + g_pp[base + 64] + g_pp[base + 128] + g_pp[base + 192])
                  * (1.0f / 4096.0f);
        xs[i][n] = v;
        my[n] = v;
    }
    __syncthreads();

    float d[64];
    float mx = -1e30f;
    #pragma unroll
    for (int j = 0; j < 64; ++j) {
        float s = 0.f;
        #pragma unroll
        for (int n = 0; n < 16; ++n) s += my[n] * xs[j][n];
        s *= 0.25f;
        d[j] = s;
        mx = fmaxf(mx, s);
    }
    float sum = 0.f;
    #pragma unroll
    for (int j = 0; j < 64; ++j) { d[j] = expf(d[j] - mx); sum += d[j]; }
    float inv = 1.0f / sum;

    __nv_bfloat16* ah = (__nv_bfloat16*)g_attn_h4;
    __nv_bfloat16* al = (__nv_bfloat16*)g_attn_l4;
    size_t rb = ((size_t)b * 64 + i) * 64;
    #pragma unroll
    for (int j = 0; j < 64; ++j) {
        float a = d[j] * inv;
        __nv_bfloat16 h = __float2bfloat16(a);
        float hv = __bfloat162float(h);
        ah[rb + j] = h;
        al[rb + j] = __float2bfloat16(a - hv);
    }
}

// ---------------------------------------------------------------------------
// Kernel C: mma.sync bf16 GEMM + fast GELU.
// grid = (HW/128, B), 256 threads (8 warps). D[128x64] = X[128x64] * Attn^T.
// Warp w owns M-rows [w*16, w*16+16). Split: D = Xh*Ah + Xl*Ah + Xh*Al.
//
// SMEM (static 48KB): BH [64][64] bf16 (8KB), BL (8KB),
//                     XH [128][64] bf16 (16KB), XL (16KB)
// A/B tiles: 128B rows, 16B-granular XOR swizzle.
// Epilogue: each warp re-uses ITS OWN rows of XH/XL (4KB, warp-private)
// to stage the fp32 output tile, then emits coalesced STG.128.
// ---------------------------------------------------------------------------
#define OFF_BH 0
#define OFF_BL 8192
#define OFF_XH 16384
#define OFF_XL 32768

// stage addressing: warp-local row r (0..15), 256B rows, 16B-chunk XOR by (r&7)
__device__ __forceinline__ uint32_t stage_off(int wid, int r, uint32_t byteoff) {
    uint32_t base = (r < 8 ? OFF_XH : OFF_XL) + wid * 2048 + (r & 7) * 256;
    return base + (byteoff ^ ((uint32_t)(r & 7) << 4));
}

__global__ void __launch_bounds__(256, 3) gemm_kernel(const float* __restrict__ x,
                                                      float* __restrict__ out)
{
    __shared__ __align__(128) unsigned char smem[49152];
    uint32_t sb = smem_u32(smem);
    int tid = threadIdx.x;
    int wid = tid >> 5, lid = tid & 31;
    int b = blockIdx.y;
    int s0 = blockIdx.x * TILE_S;

    // ---- issue all global loads first (max MLP)
    const float4* gx = (const float4*)(x + ((size_t)b * HW + s0) * Cc);
    float4 v[8];
    #pragma unroll
    for (int it = 0; it < 8; ++it) v[it] = __ldcs(&gx[tid + 256 * it]);

    const uint4* gh = g_attn_h4 + (size_t)b * 512;
    const uint4* gl = g_attn_l4 + (size_t)b * 512;
    uint4 bh0 = gh[tid], bh1 = gh[tid + 256];
    uint4 bl0 = gl[tid], bl1 = gl[tid + 256];

    // ---- convert x tile to bf16 hi/lo, store swizzled
    #pragma unroll
    for (int it = 0; it < 8; ++it) {
        int f = tid + 256 * it;               // float4 index (2048 total)
        uint32_t p0 = pack_bf(v[it].x, v[it].y);
        uint32_t p1 = pack_bf(v[it].z, v[it].w);
        float hx = __uint_as_float(p0 << 16);
        float hy = __uint_as_float(p0 & 0xFFFF0000u);
        float hz = __uint_as_float(p1 << 16);
        float hw = __uint_as_float(p1 & 0xFFFF0000u);
        uint32_t q0 = pack_bf(v[it].x - hx, v[it].y - hy);
        uint32_t q1 = pack_bf(v[it].z - hz, v[it].w - hw);
        int row = f >> 4;
        uint32_t kbyte = (f & 15) * 8;
        uint32_t off = row * 128 + (kbyte ^ ((row & 7) << 4));
        *(uint2*)(smem + OFF_XH + off) = make_uint2(p0, p1);
        *(uint2*)(smem + OFF_XL + off) = make_uint2(q0, q1);
    }

    // ---- attn tiles, store swizzled
    {
        int m0 = tid, m1 = tid + 256;
        int row0 = m0 >> 3, row1 = m1 >> 3;
        uint32_t kb0 = (m0 & 7) * 16, kb1 = (m1 & 7) * 16;
        uint32_t o0 = row0 * 128 + (kb0 ^ ((row0 & 7) << 4));
        uint32_t o1 = row1 * 128 + (kb1 ^ ((row1 & 7) << 4));
        *(uint4*)(smem + OFF_BH + o0) = bh0;
        *(uint4*)(smem + OFF_BH + o1) = bh1;
        *(uint4*)(smem + OFF_BL + o0) = bl0;
        *(uint4*)(smem + OFF_BL + o1) = bl1;
    }
    __syncthreads();

    // ---- MMA mainloop
    float acc[8][4];
    #pragma unroll
    for (int i = 0; i < 8; ++i)
        #pragma unroll
        for (int j = 0; j < 4; ++j) acc[i][j] = 0.f;

    uint32_t a_row = wid * 16 + (lid & 15);
    uint32_t a_k16 = (lid >> 4) & 1;
    uint32_t b_nrow_lo = (lid & 7) + ((lid >> 4) & 1) * 8;
    uint32_t b_k16 = (lid >> 3) & 1;

    #pragma unroll
    for (int kc = 0; kc < 4; ++kc) {
        uint32_t kb = kc * 32;
        uint32_t akb = kb + a_k16 * 16;
        uint32_t a_off = a_row * 128 + (akb ^ ((a_row & 7) << 4));
        uint32_t A0, A1, A2, A3, L0, L1, L2, L3;
        ldsm_x4(A0, A1, A2, A3, sb + OFF_XH + a_off);
        ldsm_x4(L0, L1, L2, L3, sb + OFF_XL + a_off);

        #pragma unroll
        for (int ntp = 0; ntp < 4; ++ntp) {
            uint32_t bn = ntp * 16 + b_nrow_lo;
            uint32_t bkb = kb + b_k16 * 16;
            uint32_t b_off = bn * 128 + (bkb ^ ((bn & 7) << 4));
            uint32_t h0, h1, h2, h3, l0, l1, l2, l3;
            ldsm_x4(h0, h1, h2, h3, sb + OFF_BH + b_off);
            ldsm_x4(l0, l1, l2, l3, sb + OFF_BL + b_off);

            float* c0 = acc[ntp * 2];
            float* c1 = acc[ntp * 2 + 1];
            mma_bf16(c0, A0, A1, A2, A3, h0, h1);
            mma_bf16(c0, L0, L1, L2, L3, h0, h1);
            mma_bf16(c0, A0, A1, A2, A3, l0, l1);
            mma_bf16(c1, A0, A1, A2, A3, h2, h3);
            mma_bf16(c1, L0, L1, L2, L3, h2, h3);
            mma_bf16(c1, A0, A1, A2, A3, l2, l3);
        }
    }

    // ---- epilogue: GELU in regs, stage in warp-private smem, STG.128 out.
    // Fragment (nt): lane l -> local rows rl=(l>>2), rl+8; cols nt*8+(l&3)*2.
    {
        int rl = lid >> 2;
        uint32_t cb = (uint32_t)(lid & 3) * 8;    // byte offset of float2 in row
        #pragma unroll
        for (int nt = 0; nt < 8; ++nt) {
            uint32_t byteoff = nt * 32 + cb;
            float2 v0, v1;
            v0.x = gelu_fast(acc[nt][0]);
            v0.y = gelu_fast(acc[nt][1]);
            v1.x = gelu_fast(acc[nt][2]);
            v1.y = gelu_fast(acc[nt][3]);
            *(float2*)(smem + stage_off(wid, rl,     byteoff)) = v0;
            *(float2*)(smem + stage_off(wid, rl + 8, byteoff)) = v1;
        }
        __syncwarp();

        // read back + coalesced store: instr 'it' writes 512B contiguous
        float* ob = out + ((size_t)b * HW + s0 + wid * 16) * Cc;
        #pragma unroll
        for (int it = 0; it < 8; ++it) {
            int r = it * 2 + (lid >> 4);          // local row 0..15
            uint32_t chunk = (uint32_t)(lid & 15) * 16;
            uint4 d = *(uint4*)(smem + stage_off(wid, r, chunk));
            __stcs((uint4*)((char*)ob + it * 512 + lid * 16), d);
        }
    }
}

// ---------------------------------------------------------------------------
extern "C" void kernel_launch(void* const* d_in, const int* in_sizes, int n_in,
                              void* d_out, int out_size)
{
    const float* x = (const float*)d_in[0];
    float* out = (float*)d_out;
    (void)in_sizes; (void)n_in; (void)out_size;

    pool_kernel<<<1024, 256>>>(x);
    attn_kernel<<<B_, 64>>>();
    gemm_kernel<<<dim3(HW / TILE_S, B_), 256>>>(x, out);
}

// round 7
// speedup vs baseline: 1.3491x; 1.0778x over previous
#include <cuda_runtime.h>
#include <cuda_fp16.h>
#include <cuda_bf16.h>
#include <cstdint>

// ---------------------------------------------------------------------------
// CFModule_12575664243188 on sm_103a (compute_103-safe: no tcgen05):
//   x: [B=16, H=256, W=256, C=64] fp32
//   pooled = adaptive_avg_pool 4x4  -> [B,16,64]
//   dots[b,i,j] = 0.25 * <pooled[:,i], pooled[:,j]>; attn = softmax_j
//   out[b,s,t] = gelu( sum_c x[b,s,c] * attn[b,t,c] )
//
// Main GEMM: mma.sync m16n8k16 fp16, x split hi+lo (2 terms vs fp16-rounded
// attn): D = (Xh + Xl) * Ah, fp32 accumulate. Error ~ attn fp16 rounding
// (~2e-4 rel), under the 1e-3 gate. GELU via tanh.approx.f32; output staged
// through smem for coalesced STG.128.
// ---------------------------------------------------------------------------

#define B_    16
#define Hc    256
#define Wc    256
#define Cc    64
#define HW    (Hc*Wc)          // 65536
#define TILE_S 128

// --------------------------- global scratch --------------------------------
__device__ float g_pp[1024 * 64];                    // pool partials [b][n][q][c]
__device__ uint4 g_attn_h4[B_ * 512];                // attn fp16 [b][t][c]

// --------------------------- helpers ---------------------------------------
__device__ __forceinline__ uint32_t smem_u32(const void* p) {
    uint32_t a;
    asm("{ .reg .u64 t; cvta.to.shared.u64 t, %1; cvt.u32.u64 %0, t; }"
        : "=r"(a) : "l"(p));
    return a;
}

__device__ __forceinline__ void ldsm_x4(uint32_t& r0, uint32_t& r1,
                                        uint32_t& r2, uint32_t& r3, uint32_t addr) {
    asm volatile("ldmatrix.sync.aligned.m8n8.x4.shared.b16 {%0,%1,%2,%3}, [%4];"
                 : "=r"(r0), "=r"(r1), "=r"(r2), "=r"(r3) : "r"(addr));
}

__device__ __forceinline__ void mma_f16(float* c, uint32_t a0, uint32_t a1,
                                        uint32_t a2, uint32_t a3,
                                        uint32_t b0, uint32_t b1) {
    asm volatile(
        "mma.sync.aligned.m16n8k16.row.col.f32.f16.f16.f32 "
        "{%0,%1,%2,%3}, {%4,%5,%6,%7}, {%8,%9}, {%0,%1,%2,%3};"
        : "+f"(c[0]), "+f"(c[1]), "+f"(c[2]), "+f"(c[3])
        : "r"(a0), "r"(a1), "r"(a2), "r"(a3), "r"(b0), "r"(b1));
}

// GELU via HW tanh: 0.5*v*(1 + tanh(0.79788456*(v + 0.044715 v^3)))
__device__ __forceinline__ float gelu_fast(float v) {
    float v2 = v * v;
    float p = fmaf(0.0356774081f, v2, 0.7978845608f);
    float arg = p * v;
    float t;
    asm("tanh.approx.f32 %0, %1;" : "=f"(t) : "f"(arg));
    float h = 0.5f * v;
    return fmaf(h, t, h);
}

// ---------------------------------------------------------------------------
// Kernel A: pool partials. grid = 1024 (b*64 + n*4 + q), 256 threads.
// ---------------------------------------------------------------------------
__global__ void __launch_bounds__(256) pool_kernel(const float* __restrict__ x)
{
    int blk = blockIdx.x;
    int q = blk & 3, n = (blk >> 2) & 15, b = blk >> 6;
    int ph = n >> 2, pw = n & 3;
    int tid = threadIdx.x;

    float4 acc = make_float4(0.f, 0.f, 0.f, 0.f);
    for (int hh = 0; hh < 16; ++hh) {
        int h = ph * 64 + q * 16 + hh;
        const float4* row = (const float4*)(
            x + (((size_t)b * Hc + h) * Wc + (size_t)pw * 64) * Cc);
        #pragma unroll
        for (int it = 0; it < 4; ++it) {
            float4 v = row[tid + 256 * it];
            acc.x += v.x; acc.y += v.y; acc.z += v.z; acc.w += v.w;
        }
    }
    __shared__ float4 sm[256];
    sm[tid] = acc;
    __syncthreads();
    if (tid < 64) {
        int r = tid >> 2, j = tid & 3;
        float s = 0.f;
        #pragma unroll
        for (int w = 0; w < 16; ++w)
            s += ((const float*)&sm[r + 16 * w])[j];
        g_pp[blk * 64 + tid] = s;
    }
}

// ---------------------------------------------------------------------------
// Kernel B: merge partials, gram + softmax, emit fp16 attn.
// ---------------------------------------------------------------------------
__global__ void __launch_bounds__(64) attn_kernel()
{
    int b = blockIdx.x;
    int i = threadIdx.x;
    __shared__ float xs[64][17];
    float my[16];
    #pragma unroll
    for (int n = 0; n < 16; ++n) {
        int base = ((b * 16 + n) * 4) * 64 + i;
        float v = (g_pp[base] + g_pp[base + 64] + g_pp[base + 128] + g_pp[base + 192])
                  * (1.0f / 4096.0f);
        xs[i][n] = v;
        my[n] = v;
    }
    __syncthreads();

    float d[64];
    float mx = -1e30f;
    #pragma unroll
    for (int j = 0; j < 64; ++j) {
        float s = 0.f;
        #pragma unroll
        for (int n = 0; n < 16; ++n) s += my[n] * xs[j][n];
        s *= 0.25f;
        d[j] = s;
        mx = fmaxf(mx, s);
    }
    float sum = 0.f;
    #pragma unroll
    for (int j = 0; j < 64; ++j) { d[j] = expf(d[j] - mx); sum += d[j]; }
    float inv = 1.0f / sum;

    __half* ah = (__half*)g_attn_h4;
    size_t rb = ((size_t)b * 64 + i) * 64;
    #pragma unroll
    for (int j = 0; j < 64; ++j)
        ah[rb + j] = __float2half_rn(d[j] * inv);
}

// ---------------------------------------------------------------------------
// Kernel C: mma.sync fp16 GEMM + fast GELU.
// grid = (HW/128, B), 256 threads (8 warps). D[128x64] = X[128x64] * Attn^T.
// Warp w owns M-rows [w*16, w*16+16). D = Xh*Ah + Xl*Ah.
//
// SMEM (static 40KB): BH [64][64] f16 (8KB), XH [128][64] f16 (16KB), XL (16KB)
// Tiles: 128B rows, 16B-granular XOR swizzle.
// Epilogue: warp-private stage region inside XH/XL, coalesced STG.128.
// ---------------------------------------------------------------------------
#define OFF_BH 0
#define OFF_XH 8192
#define OFF_XL 24576

// stage addressing: warp-local row r (0..15), 256B rows, 16B-chunk XOR by (r&7)
__device__ __forceinline__ uint32_t stage_off(int wid, int r, uint32_t byteoff) {
    uint32_t base = (r < 8 ? OFF_XH : OFF_XL) + wid * 2048 + (r & 7) * 256;
    return base + (byteoff ^ ((uint32_t)(r & 7) << 4));
}

__global__ void __launch_bounds__(256, 3) gemm_kernel(const float* __restrict__ x,
                                                      float* __restrict__ out)
{
    __shared__ __align__(128) unsigned char smem[40960];
    uint32_t sb = smem_u32(smem);
    int tid = threadIdx.x;
    int wid = tid >> 5, lid = tid & 31;
    int b = blockIdx.y;
    int s0 = blockIdx.x * TILE_S;

    // ---- issue all global loads first (max MLP)
    const float4* gx = (const float4*)(x + ((size_t)b * HW + s0) * Cc);
    float4 v[8];
    #pragma unroll
    for (int it = 0; it < 8; ++it) v[it] = __ldcs(&gx[tid + 256 * it]);

    const uint4* gh = g_attn_h4 + (size_t)b * 512;
    uint4 bh0 = gh[tid], bh1 = gh[tid + 256];

    // ---- convert x tile to fp16 hi/lo, store swizzled
    #pragma unroll
    for (int it = 0; it < 8; ++it) {
        int f = tid + 256 * it;               // float4 index (2048 total)
        __half2 h0 = __float22half2_rn(make_float2(v[it].x, v[it].y));
        __half2 h1 = __float22half2_rn(make_float2(v[it].z, v[it].w));
        float2 f0 = __half22float2(h0);
        float2 f1 = __half22float2(h1);
        __half2 l0 = __float22half2_rn(make_float2(v[it].x - f0.x, v[it].y - f0.y));
        __half2 l1 = __float22half2_rn(make_float2(v[it].z - f1.x, v[it].w - f1.y));
        int row = f >> 4;
        uint32_t kbyte = (f & 15) * 8;
        uint32_t off = row * 128 + (kbyte ^ ((row & 7) << 4));
        *(uint2*)(smem + OFF_XH + off) =
            make_uint2(*(uint32_t*)&h0, *(uint32_t*)&h1);
        *(uint2*)(smem + OFF_XL + off) =
            make_uint2(*(uint32_t*)&l0, *(uint32_t*)&l1);
    }

    // ---- attn tile, store swizzled
    {
        int m0 = tid, m1 = tid + 256;
        int row0 = m0 >> 3, row1 = m1 >> 3;
        uint32_t kb0 = (m0 & 7) * 16, kb1 = (m1 & 7) * 16;
        uint32_t o0 = row0 * 128 + (kb0 ^ ((row0 & 7) << 4));
        uint32_t o1 = row1 * 128 + (kb1 ^ ((row1 & 7) << 4));
        *(uint4*)(smem + OFF_BH + o0) = bh0;
        *(uint4*)(smem + OFF_BH + o1) = bh1;
    }
    __syncthreads();

    // ---- MMA mainloop
    float acc[8][4];
    #pragma unroll
    for (int i = 0; i < 8; ++i)
        #pragma unroll
        for (int j = 0; j < 4; ++j) acc[i][j] = 0.f;

    uint32_t a_row = wid * 16 + (lid & 15);
    uint32_t a_k16 = (lid >> 4) & 1;
    uint32_t b_nrow_lo = (lid & 7) + ((lid >> 4) & 1) * 8;
    uint32_t b_k16 = (lid >> 3) & 1;

    #pragma unroll
    for (int kc = 0; kc < 4; ++kc) {
        uint32_t kb = kc * 32;
        uint32_t akb = kb + a_k16 * 16;
        uint32_t a_off = a_row * 128 + (akb ^ ((a_row & 7) << 4));
        uint32_t A0, A1, A2, A3, L0, L1, L2, L3;
        ldsm_x4(A0, A1, A2, A3, sb + OFF_XH + a_off);
        ldsm_x4(L0, L1, L2, L3, sb + OFF_XL + a_off);

        #pragma unroll
        for (int ntp = 0; ntp < 4; ++ntp) {
            uint32_t bn = ntp * 16 + b_nrow_lo;
            uint32_t bkb = kb + b_k16 * 16;
            uint32_t b_off = bn * 128 + (bkb ^ ((bn & 7) << 4));
            uint32_t h0, h1, h2, h3;
            ldsm_x4(h0, h1, h2, h3, sb + OFF_BH + b_off);

            float* c0 = acc[ntp * 2];
            float* c1 = acc[ntp * 2 + 1];
            mma_f16(c0, A0, A1, A2, A3, h0, h1);
            mma_f16(c0, L0, L1, L2, L3, h0, h1);
            mma_f16(c1, A0, A1, A2, A3, h2, h3);
            mma_f16(c1, L0, L1, L2, L3, h2, h3);
        }
    }

    // ---- epilogue: GELU in regs, stage in warp-private smem, STG.128 out.
    {
        int rl = lid >> 2;
        uint32_t cb = (uint32_t)(lid & 3) * 8;    // byte offset of float2 in row
        #pragma unroll
        for (int nt = 0; nt < 8; ++nt) {
            uint32_t byteoff = nt * 32 + cb;
            float2 v0, v1;
            v0.x = gelu_fast(acc[nt][0]);
            v0.y = gelu_fast(acc[nt][1]);
            v1.x = gelu_fast(acc[nt][2]);
            v1.y = gelu_fast(acc[nt][3]);
            *(float2*)(smem + stage_off(wid, rl,     byteoff)) = v0;
            *(float2*)(smem + stage_off(wid, rl + 8, byteoff)) = v1;
        }
        __syncwarp();

        // read back + coalesced store: instr 'it' writes 512B contiguous
        float* ob = out + ((size_t)b * HW + s0 + wid * 16) * Cc;
        #pragma unroll
        for (int it = 0; it < 8; ++it) {
            int r = it * 2 + (lid >> 4);          // local row 0..15
            uint32_t chunk = (uint32_t)(lid & 15) * 16;
            uint4 d = *(uint4*)(smem + stage_off(wid, r, chunk));
            __stcs((uint4*)((char*)ob + it * 512 + lid * 16), d);
        }
    }
}

// ---------------------------------------------------------------------------
extern "C" void kernel_launch(void* const* d_in, const int* in_sizes, int n_in,
                              void* d_out, int out_size)
{
    const float* x = (const float*)d_in[0];
    float* out = (float*)d_out;
    (void)in_sizes; (void)n_in; (void)out_size;

    pool_kernel<<<1024, 256>>>(x);
    attn_kernel<<<B_, 64>>>();
    gemm_kernel<<<dim3(HW / TILE_S, B_), 256>>>(x, out);
}

// round 8
// speedup vs baseline: 1.4213x; 1.0535x over previous
#include <cuda_runtime.h>
#include <cuda_fp16.h>
#include <cstdint>

// ---------------------------------------------------------------------------
// CFModule_12575664243188 on sm_103a (compute_103-safe: no tcgen05):
//   x: [B=16, H=256, W=256, C=64] fp32
//   pooled = adaptive_avg_pool 4x4  -> [B,16,64]
//   dots[b,i,j] = 0.25 * <pooled[:,i], pooled[:,j]>; attn = softmax_j
//   out[b,s,t] = gelu( sum_c x[b,s,c] * attn[b,t,c] )
//
// Main GEMM: pure fp16 mma.sync m16n8k16 (x and attn both fp16-rounded,
// fp32 accumulate). Output rel err ~3e-4 (L2), under the 1e-3 gate.
// GELU via tanh.approx.f32; output staged through smem for STG.128.
// ---------------------------------------------------------------------------

#define B_    16
#define Hc    256
#define Wc    256
#define Cc    64
#define HW    (Hc*Wc)          // 65536
#define TILE_S 128

// --------------------------- global scratch --------------------------------
__device__ float g_pp[1024 * 64];                    // pool partials [b][n][q][c]
__device__ uint4 g_attn_h4[B_ * 512];                // attn fp16 [b][t][c]

// --------------------------- helpers ---------------------------------------
__device__ __forceinline__ uint32_t smem_u32(const void* p) {
    uint32_t a;
    asm("{ .reg .u64 t; cvta.to.shared.u64 t, %1; cvt.u32.u64 %0, t; }"
        : "=r"(a) : "l"(p));
    return a;
}

__device__ __forceinline__ void ldsm_x4(uint32_t& r0, uint32_t& r1,
                                        uint32_t& r2, uint32_t& r3, uint32_t addr) {
    asm volatile("ldmatrix.sync.aligned.m8n8.x4.shared.b16 {%0,%1,%2,%3}, [%4];"
                 : "=r"(r0), "=r"(r1), "=r"(r2), "=r"(r3) : "r"(addr));
}

__device__ __forceinline__ void mma_f16(float* c, uint32_t a0, uint32_t a1,
                                        uint32_t a2, uint32_t a3,
                                        uint32_t b0, uint32_t b1) {
    asm volatile(
        "mma.sync.aligned.m16n8k16.row.col.f32.f16.f16.f32 "
        "{%0,%1,%2,%3}, {%4,%5,%6,%7}, {%8,%9}, {%0,%1,%2,%3};"
        : "+f"(c[0]), "+f"(c[1]), "+f"(c[2]), "+f"(c[3])
        : "r"(a0), "r"(a1), "r"(a2), "r"(a3), "r"(b0), "r"(b1));
}

// GELU via HW tanh: 0.5*v*(1 + tanh(0.79788456*(v + 0.044715 v^3)))
__device__ __forceinline__ float gelu_fast(float v) {
    float v2 = v * v;
    float p = fmaf(0.0356774081f, v2, 0.7978845608f);
    float arg = p * v;
    float t;
    asm("tanh.approx.f32 %0, %1;" : "=f"(t) : "f"(arg));
    float h = 0.5f * v;
    return fmaf(h, t, h);
}

// ---------------------------------------------------------------------------
// Kernel A: pool partials. grid = 1024 (b*64 + n*4 + q), 256 threads.
// ---------------------------------------------------------------------------
__global__ void __launch_bounds__(256) pool_kernel(const float* __restrict__ x)
{
    int blk = blockIdx.x;
    int q = blk & 3, n = (blk >> 2) & 15, b = blk >> 6;
    int ph = n >> 2, pw = n & 3;
    int tid = threadIdx.x;

    float4 acc = make_float4(0.f, 0.f, 0.f, 0.f);
    for (int hh = 0; hh < 16; ++hh) {
        int h = ph * 64 + q * 16 + hh;
        const float4* row = (const float4*)(
            x + (((size_t)b * Hc + h) * Wc + (size_t)pw * 64) * Cc);
        #pragma unroll
        for (int it = 0; it < 4; ++it) {
            float4 v = row[tid + 256 * it];
            acc.x += v.x; acc.y += v.y; acc.z += v.z; acc.w += v.w;
        }
    }
    __shared__ float4 sm[256];
    sm[tid] = acc;
    __syncthreads();
    if (tid < 64) {
        int r = tid >> 2, j = tid & 3;
        float s = 0.f;
        #pragma unroll
        for (int w = 0; w < 16; ++w)
            s += ((const float*)&sm[r + 16 * w])[j];
        g_pp[blk * 64 + tid] = s;
    }
}

// ---------------------------------------------------------------------------
// Kernel B: merge partials, gram + softmax, emit fp16 attn.
// ---------------------------------------------------------------------------
__global__ void __launch_bounds__(64) attn_kernel()
{
    int b = blockIdx.x;
    int i = threadIdx.x;
    __shared__ float xs[64][17];
    float my[16];
    #pragma unroll
    for (int n = 0; n < 16; ++n) {
        int base = ((b * 16 + n) * 4) * 64 + i;
        float v = (g_pp[base] + g_pp[base + 64] + g_pp[base + 128] + g_pp[base + 192])
                  * (1.0f / 4096.0f);
        xs[i][n] = v;
        my[n] = v;
    }
    __syncthreads();

    float d[64];
    float mx = -1e30f;
    #pragma unroll
    for (int j = 0; j < 64; ++j) {
        float s = 0.f;
        #pragma unroll
        for (int n = 0; n < 16; ++n) s += my[n] * xs[j][n];
        s *= 0.25f;
        d[j] = s;
        mx = fmaxf(mx, s);
    }
    float sum = 0.f;
    #pragma unroll
    for (int j = 0; j < 64; ++j) { d[j] = expf(d[j] - mx); sum += d[j]; }
    float inv = 1.0f / sum;

    __half* ah = (__half*)g_attn_h4;
    size_t rb = ((size_t)b * 64 + i) * 64;
    #pragma unroll
    for (int j = 0; j < 64; ++j)
        ah[rb + j] = __float2half_rn(d[j] * inv);
}

// ---------------------------------------------------------------------------
// Kernel C: fp16 mma.sync GEMM + fast GELU.
// grid = (HW/128, B), 256 threads (8 warps). D[128x64] = X[128x64] * Attn^T.
// Warp w owns M-rows [w*16, w*16+16).
//
// SMEM (static 32KB): BH [64][64] f16 (8KB), XH [128][64] f16 (16KB).
// Tiles: 128B rows, 16B-granular XOR swizzle.
// Epilogue: after a __syncthreads, the whole 32KB is reused as a per-warp
// staging area (4KB/warp) for the fp32 output tile -> coalesced STG.128.
// ---------------------------------------------------------------------------
#define OFF_BH 0
#define OFF_XH 8192

// stage addressing: warp-local row r (0..15), 256B rows, 16B-chunk XOR by (r&7)
__device__ __forceinline__ uint32_t stage_off(int wid, int r, uint32_t byteoff) {
    uint32_t base = wid * 4096 + r * 256;
    return base + (byteoff ^ ((uint32_t)(r & 7) << 4));
}

__global__ void __launch_bounds__(256, 4) gemm_kernel(const float* __restrict__ x,
                                                      float* __restrict__ out)
{
    __shared__ __align__(128) unsigned char smem[32768];
    uint32_t sb = smem_u32(smem);
    int tid = threadIdx.x;
    int wid = tid >> 5, lid = tid & 31;
    int b = blockIdx.y;
    int s0 = blockIdx.x * TILE_S;

    // ---- issue all global loads first (max MLP)
    const float4* gx = (const float4*)(x + ((size_t)b * HW + s0) * Cc);
    float4 v[8];
    #pragma unroll
    for (int it = 0; it < 8; ++it) v[it] = __ldcs(&gx[tid + 256 * it]);

    const uint4* gh = g_attn_h4 + (size_t)b * 512;
    uint4 bh0 = gh[tid], bh1 = gh[tid + 256];

    // ---- convert x tile to fp16, store swizzled
    #pragma unroll
    for (int it = 0; it < 8; ++it) {
        int f = tid + 256 * it;               // float4 index (2048 total)
        __half2 h0 = __float22half2_rn(make_float2(v[it].x, v[it].y));
        __half2 h1 = __float22half2_rn(make_float2(v[it].z, v[it].w));
        int row = f >> 4;
        uint32_t kbyte = (f & 15) * 8;
        uint32_t off = row * 128 + (kbyte ^ ((row & 7) << 4));
        *(uint2*)(smem + OFF_XH + off) =
            make_uint2(*(uint32_t*)&h0, *(uint32_t*)&h1);
    }

    // ---- attn tile, store swizzled
    {
        int m0 = tid, m1 = tid + 256;
        int row0 = m0 >> 3, row1 = m1 >> 3;
        uint32_t kb0 = (m0 & 7) * 16, kb1 = (m1 & 7) * 16;
        uint32_t o0 = row0 * 128 + (kb0 ^ ((row0 & 7) << 4));
        uint32_t o1 = row1 * 128 + (kb1 ^ ((row1 & 7) << 4));
        *(uint4*)(smem + OFF_BH + o0) = bh0;
        *(uint4*)(smem + OFF_BH + o1) = bh1;
    }
    __syncthreads();

    // ---- MMA mainloop (32 HMMA / warp)
    float acc[8][4];
    #pragma unroll
    for (int i = 0; i < 8; ++i)
        #pragma unroll
        for (int j = 0; j < 4; ++j) acc[i][j] = 0.f;

    uint32_t a_row = wid * 16 + (lid & 15);
    uint32_t a_k16 = (lid >> 4) & 1;
    uint32_t b_nrow_lo = (lid & 7) + ((lid >> 4) & 1) * 8;
    uint32_t b_k16 = (lid >> 3) & 1;

    #pragma unroll
    for (int kc = 0; kc < 4; ++kc) {
        uint32_t kb = kc * 32;
        uint32_t akb = kb + a_k16 * 16;
        uint32_t a_off = a_row * 128 + (akb ^ ((a_row & 7) << 4));
        uint32_t A0, A1, A2, A3;
        ldsm_x4(A0, A1, A2, A3, sb + OFF_XH + a_off);

        #pragma unroll
        for (int ntp = 0; ntp < 4; ++ntp) {
            uint32_t bn = ntp * 16 + b_nrow_lo;
            uint32_t bkb = kb + b_k16 * 16;
            uint32_t b_off = bn * 128 + (bkb ^ ((bn & 7) << 4));
            uint32_t h0, h1, h2, h3;
            ldsm_x4(h0, h1, h2, h3, sb + OFF_BH + b_off);

            mma_f16(acc[ntp * 2],     A0, A1, A2, A3, h0, h1);
            mma_f16(acc[ntp * 2 + 1], A0, A1, A2, A3, h2, h3);
        }
    }

    // tiles fully consumed; reuse ALL smem as stage
    __syncthreads();

    // ---- epilogue: GELU in regs, stage in warp-private smem, STG.128 out.
    {
        int rl = lid >> 2;
        uint32_t cb = (uint32_t)(lid & 3) * 8;    // byte offset of float2 in row
        #pragma unroll
        for (int nt = 0; nt < 8; ++nt) {
            uint32_t byteoff = nt * 32 + cb;
            float2 v0, v1;
            v0.x = gelu_fast(acc[nt][0]);
            v0.y = gelu_fast(acc[nt][1]);
            v1.x = gelu_fast(acc[nt][2]);
            v1.y = gelu_fast(acc[nt][3]);
            *(float2*)(smem + stage_off(wid, rl,     byteoff)) = v0;
            *(float2*)(smem + stage_off(wid, rl + 8, byteoff)) = v1;
        }
        __syncwarp();

        // read back + coalesced store: instr 'it' writes 512B contiguous
        float* ob = out + ((size_t)b * HW + s0 + wid * 16) * Cc;
        #pragma unroll
        for (int it = 0; it < 8; ++it) {
            int r = it * 2 + (lid >> 4);          // local row 0..15
            uint32_t chunk = (uint32_t)(lid & 15) * 16;
            uint4 d = *(uint4*)(smem + stage_off(wid, r, chunk));
            __stcs((uint4*)((char*)ob + it * 512 + lid * 16), d);
        }
    }
}

// ---------------------------------------------------------------------------
extern "C" void kernel_launch(void* const* d_in, const int* in_sizes, int n_in,
                              void* d_out, int out_size)
{
    const float* x = (const float*)d_in[0];
    float* out = (float*)d_out;
    (void)in_sizes; (void)n_in; (void)out_size;

    pool_kernel<<<1024, 256>>>(x);
    attn_kernel<<<B_, 64>>>();
    gemm_kernel<<<dim3(HW / TILE_S, B_), 256>>>(x, out);
}